// round 2
// baseline (speedup 1.0000x reference)
#include <cuda_runtime.h>
#include <math.h>

#define N_ENT 4096
#define BATCH 4
#define NHID  3
#define NT    512
#define NJ    8                      // columns per thread (512*8 = 4096)
#define NR    2                      // rows per tile
#define NTILES (BATCH*N_ENT/NR)      // 8192

// ---------------- device scratch ----------------
__device__ float4 g_tabA[N_ENT];        // p, q, dst, h0
__device__ float2 g_tabB[N_ENT];        // h1, h2
__device__ float  g_src[N_ENT];
__device__ float4 g_rowc[N_ENT];        // u, v, w0, thr(=-src)
__device__ float  g_x[BATCH*N_ENT*NHID];

// ---------------- K1: h = emb@W, src/dst per node ----------------
__global__ void k_node(const float* __restrict__ emb,
                       const float* __restrict__ W,
                       const float* __restrict__ a) {
    __shared__ float sW[192];
    __shared__ float sa[6];
    int t = threadIdx.x;
    if (t < 192) sW[t] = W[t];
    if (t < 6)   sa[t] = a[t];
    __syncthreads();

    int i = blockIdx.x * blockDim.x + t;
    const float4* ev = (const float4*)(emb + (size_t)i * 64);
    float h0 = 0.f, h1 = 0.f, h2 = 0.f;
#pragma unroll
    for (int k4 = 0; k4 < 16; k4++) {
        float4 e = ev[k4];
        int k = k4 * 4;
        h0 += e.x*sW[k*3+0] + e.y*sW[k*3+3] + e.z*sW[k*3+6] + e.w*sW[k*3+9];
        h1 += e.x*sW[k*3+1] + e.y*sW[k*3+4] + e.z*sW[k*3+7] + e.w*sW[k*3+10];
        h2 += e.x*sW[k*3+2] + e.y*sW[k*3+5] + e.z*sW[k*3+8] + e.w*sW[k*3+11];
    }
    float src = h0*sa[0] + h1*sa[1] + h2*sa[2];
    float dst = h0*sa[3] + h1*sa[4] + h2*sa[5];
    g_tabA[i] = make_float4(0.f, 0.f, dst, h0);
    g_tabB[i] = make_float2(h1, h2);
    g_src[i]  = src;
}

// ---------------- K2: fused dstmax reduction + per-node softmax factors ----
__global__ void k_prep() {
    __shared__ float sm[1024];
    int t = threadIdx.x;
    float m = -1e30f;
#pragma unroll
    for (int k = 0; k < 4; k++) m = fmaxf(m, g_tabA[t + k*1024].z);
    sm[t] = m;
    __syncthreads();
    for (int s = 512; s > 0; s >>= 1) {
        if (t < s) sm[t] = fmaxf(sm[t], sm[t+s]);
        __syncthreads();
    }
    float dm = sm[0];
#pragma unroll
    for (int k = 0; k < 4; k++) {
        int i = t + k*1024;
        float4 tA = g_tabA[i];
        float dst = tA.z;
        tA.x = expf(dst - dm);              // p_j (<=1)
        tA.y = expf(0.2f * (dst - dm));     // q_j (<=1)
        g_tabA[i] = tA;

        float src = g_src[i];
        float z   = src + dm;
        float lz  = (z > 0.f) ? z : 0.2f * z;
        float mm  = fmaxf(lz, 9e-15f);      // safe row max (adj-independent)
        g_rowc[i] = make_float4(expf(z - mm), expf(0.2f*z - mm),
                                expf(9e-15f - mm), -src);
    }
}

// ---------------- K3: main pass over adj (HBM-bound, pipelined) -----------
// Triple-buffered register prefetch, 2 tiles ahead; fused ELU epilogue.

#define LOADT(B0, B1, B2, B3, tl)                                              \
    {                                                                          \
        int tt = min((tl), NTILES - 1);                                        \
        int bb = tt >> 11;                                                     \
        int rr = (tt & 2047) * NR;                                             \
        const int4* ap = (const int4*)adj +                                    \
            ((((size_t)bb * N_ENT + rr) * N_ENT + j0) >> 2);                   \
        B0 = __ldg(ap);                                                        \
        B1 = __ldg(ap + 1);                                                    \
        B2 = __ldg(ap + (N_ENT/4));                                            \
        B3 = __ldg(ap + (N_ENT/4) + 1);                                        \
    }

#define PROCT(B0, B1, B2, B3, tl)                                              \
    {                                                                          \
        int bb   = (tl) >> 11;                                                 \
        int row0 = ((tl) & 2047) * NR;                                         \
        _Pragma("unroll")                                                      \
        for (int r = 0; r < NR; r++) {                                         \
            float4 rc = g_rowc[row0 + r];                                      \
            int va[NJ];                                                        \
            *(int4*)&va[0] = (r == 0) ? B0 : B2;                               \
            *(int4*)&va[4] = (r == 0) ? B1 : B3;                               \
            float a0 = 0.f, a1 = 0.f, a2 = 0.f, a3 = 0.f;                      \
            _Pragma("unroll")                                                  \
            for (int k = 0; k < NJ; k++) {                                     \
                float we = (tA[k].z > rc.w) ? (rc.x * tA[k].x)                 \
                                            : (rc.y * tA[k].y);               \
                float c  = (va[k] > 0) ? we : rc.z;                            \
                a0 += c;                                                       \
                a1 += c * tA[k].w;                                             \
                a2 += c * tB[k].x;                                             \
                a3 += c * tB[k].y;                                             \
            }                                                                  \
            red[(r*4+0)*NT + t] = a0;                                          \
            red[(r*4+1)*NT + t] = a1;                                          \
            red[(r*4+2)*NT + t] = a2;                                          \
            red[(r*4+3)*NT + t] = a3;                                          \
        }                                                                      \
        __syncthreads();                                                       \
        {   /* stage1: 16 warps -> 16 (output,chunk) partials */               \
            int o = w & 7, ch = w >> 3;                                        \
            float s = 0.f;                                                     \
            _Pragma("unroll")                                                  \
            for (int k = 0; k < 8; k++)                                        \
                s += red[o*NT + ch*256 + k*32 + lane];                         \
            _Pragma("unroll")                                                  \
            for (int off = 16; off; off >>= 1)                                 \
                s += __shfl_xor_sync(0xffffffffu, s, off);                     \
            if (lane == 0) sfin[o*2 + ch] = s;                                 \
        }                                                                      \
        __syncthreads();                                                       \
        if (w == 0) { /* stage2 + fused h'=num/den, ELU, store x */            \
            float v = (lane < 16) ? sfin[lane] : 0.f;                          \
            v += __shfl_xor_sync(0xffffffffu, v, 1);                           \
            int rsel = lane & 1;                                               \
            float d  = __shfl_sync(0xffffffffu, v, rsel*8 + 0);                \
            float n0 = __shfl_sync(0xffffffffu, v, rsel*8 + 2);                \
            float n1 = __shfl_sync(0xffffffffu, v, rsel*8 + 4);                \
            float n2 = __shfl_sync(0xffffffffu, v, rsel*8 + 6);                \
            if (lane < NR) {                                                   \
                float inv = 1.0f / d;                                          \
                float h0 = n0*inv, h1 = n1*inv, h2 = n2*inv;                   \
                h0 = (h0 > 0.f) ? h0 : (expf(h0) - 1.f);                       \
                h1 = (h1 > 0.f) ? h1 : (expf(h1) - 1.f);                       \
                h2 = (h2 > 0.f) ? h2 : (expf(h2) - 1.f);                       \
                float* xp = g_x + ((size_t)bb*N_ENT + row0 + lane)*NHID;       \
                xp[0] = h0; xp[1] = h1; xp[2] = h2;                            \
            }                                                                  \
        }                                                                      \
    }

__global__ void __launch_bounds__(NT, 1) k_main(const int* __restrict__ adj) {
    int t  = threadIdx.x;
    int j0 = t * NJ;
    int w = t >> 5, lane = t & 31;

    // per-column table, register-resident for the whole kernel
    float4 tA[NJ];
    float2 tB[NJ];
#pragma unroll
    for (int k = 0; k < NJ; k++) {
        tA[k] = g_tabA[j0 + k];
        tB[k] = g_tabB[j0 + k];
    }

    __shared__ float red[NR*4*NT];   // 16 KB
    __shared__ float sfin[16];

    int grid = gridDim.x;
    int tile = blockIdx.x;

    int4 b0a, b0b, b0c, b0d;   // slot 0
    int4 b1a, b1b, b1c, b1d;   // slot 1
    int4 b2a, b2b, b2c, b2d;   // slot 2

    LOADT(b0a, b0b, b0c, b0d, tile);
    LOADT(b1a, b1b, b1c, b1d, tile + grid);

    while (tile < NTILES) {
        LOADT(b2a, b2b, b2c, b2d, tile + 2*grid);
        PROCT(b0a, b0b, b0c, b0d, tile);
        tile += grid;
        if (tile >= NTILES) break;

        LOADT(b0a, b0b, b0c, b0d, tile + 2*grid);
        PROCT(b1a, b1b, b1c, b1d, tile);
        tile += grid;
        if (tile >= NTILES) break;

        LOADT(b1a, b1b, b1c, b1d, tile + 2*grid);
        PROCT(b2a, b2b, b2c, b2d, tile);
        tile += grid;
    }
}

// ---------------- K4: out = x @ fc1_w.T + b (vectorized) ----------------
__global__ void k_fc(const float* __restrict__ w,
                     const float* __restrict__ bias,
                     float* __restrict__ out) {
    int o = blockIdx.x;          // 100 outputs
    int t = threadIdx.x;         // 256 threads
    const float4* wr = (const float4*)(w + (size_t)o * (N_ENT*NHID));
    const float4* xv = (const float4*)g_x;
    const int K4 = (N_ENT*NHID)/4;    // 3072
    float a0 = 0.f, a1 = 0.f, a2 = 0.f, a3 = 0.f;
    for (int k = t; k < K4; k += 256) {
        float4 wv = __ldg(wr + k);
        float4 xa = xv[k];
        float4 xb = xv[K4 + k];
        float4 xc = xv[2*K4 + k];
        float4 xd = xv[3*K4 + k];
        a0 += wv.x*xa.x + wv.y*xa.y + wv.z*xa.z + wv.w*xa.w;
        a1 += wv.x*xb.x + wv.y*xb.y + wv.z*xb.z + wv.w*xb.w;
        a2 += wv.x*xc.x + wv.y*xc.y + wv.z*xc.z + wv.w*xc.w;
        a3 += wv.x*xd.x + wv.y*xd.y + wv.z*xd.z + wv.w*xd.w;
    }
    __shared__ float sr[4][256];
    sr[0][t] = a0; sr[1][t] = a1; sr[2][t] = a2; sr[3][t] = a3;
    __syncthreads();
    for (int s = 128; s > 0; s >>= 1) {
        if (t < s) {
            sr[0][t] += sr[0][t+s];
            sr[1][t] += sr[1][t+s];
            sr[2][t] += sr[2][t+s];
            sr[3][t] += sr[3][t+s];
        }
        __syncthreads();
    }
    if (t == 0) {
        float bb = bias[o];
        out[0*100 + o] = sr[0][0] + bb;
        out[1*100 + o] = sr[1][0] + bb;
        out[2*100 + o] = sr[2][0] + bb;
        out[3*100 + o] = sr[3][0] + bb;
    }
}

// ---------------- launcher ----------------
extern "C" void kernel_launch(void* const* d_in, const int* in_sizes, int n_in,
                              void* d_out, int out_size) {
    const int*   adj  = (const int*)  d_in[0];
    const float* emb  = (const float*)d_in[1];
    const float* W    = (const float*)d_in[2];
    const float* a    = (const float*)d_in[3];
    const float* fc1w = (const float*)d_in[4];
    const float* fc1b = (const float*)d_in[5];
    float* out = (float*)d_out;

    k_node<<<N_ENT/256, 256>>>(emb, W, a);
    k_prep<<<1, 1024>>>();

    int sms = 148;
    int dev = 0;
    if (cudaGetDevice(&dev) == cudaSuccess) {
        int v = 0;
        if (cudaDeviceGetAttribute(&v, cudaDevAttrMultiProcessorCount, dev) == cudaSuccess && v > 0)
            sms = v;
    }
    k_main<<<sms, NT>>>(adj);

    k_fc<<<100, 256>>>(fc1w, fc1b, out);
}

// round 3
// speedup vs baseline: 1.3968x; 1.3968x over previous
#include <cuda_runtime.h>
#include <math.h>

#define N_ENT 4096
#define BATCH 4
#define NHID  3
#define ROWS_T (BATCH*N_ENT)     // 16384
#define NT    512
#define RBLK_MAX 112

// ---------------- device scratch ----------------
__device__ float4 g_tabA[N_ENT];        // p, q, dst, h0
__device__ float2 g_tabB[N_ENT];        // h1, h2
__device__ float  g_src[N_ENT];
__device__ float4 g_rowc[N_ENT];        // u, v, w0, thr(=-src)
__device__ float  g_dstmax;
__device__ float  g_x[ROWS_T*NHID];

// ---------------- K1: h = emb@W, src/dst per node ----------------
__global__ void k_node(const float* __restrict__ emb,
                       const float* __restrict__ W,
                       const float* __restrict__ a) {
    __shared__ float sW[192];
    __shared__ float sa[6];
    int t = threadIdx.x;
    if (t < 192) sW[t] = W[t];
    if (t < 6)   sa[t] = a[t];
    __syncthreads();

    int i = blockIdx.x * blockDim.x + t;
    const float4* ev = (const float4*)(emb + (size_t)i * 64);
    float h0 = 0.f, h1 = 0.f, h2 = 0.f;
#pragma unroll
    for (int k4 = 0; k4 < 16; k4++) {
        float4 e = ev[k4];
        int k = k4 * 4;
        h0 += e.x*sW[k*3+0] + e.y*sW[k*3+3] + e.z*sW[k*3+6] + e.w*sW[k*3+9];
        h1 += e.x*sW[k*3+1] + e.y*sW[k*3+4] + e.z*sW[k*3+7] + e.w*sW[k*3+10];
        h2 += e.x*sW[k*3+2] + e.y*sW[k*3+5] + e.z*sW[k*3+8] + e.w*sW[k*3+11];
    }
    float src = h0*sa[0] + h1*sa[1] + h2*sa[2];
    float dst = h0*sa[3] + h1*sa[4] + h2*sa[5];
    g_tabA[i] = make_float4(0.f, 0.f, dst, h0);
    g_tabB[i] = make_float2(h1, h2);
    g_src[i]  = src;
}

// ---------------- K2: dstmax reduction ----------------
__global__ void k_dstmax() {
    __shared__ float sm[1024];
    int t = threadIdx.x;
    float m = -1e30f;
#pragma unroll
    for (int k = 0; k < 4; k++) m = fmaxf(m, g_tabA[t + k*1024].z);
    sm[t] = m;
    __syncthreads();
    for (int s = 512; s > 0; s >>= 1) {
        if (t < s) sm[t] = fmaxf(sm[t], sm[t+s]);
        __syncthreads();
    }
    if (t == 0) g_dstmax = sm[0];
}

// ---------------- K3: per-node softmax factors ----------------
__global__ void k_consts() {
    int i = blockIdx.x * blockDim.x + threadIdx.x;
    float dm  = g_dstmax;
    float4 tA = g_tabA[i];
    float dst = tA.z;
    tA.x = expf(dst - dm);              // p_j (<=1)
    tA.y = expf(0.2f * (dst - dm));     // q_j (<=1)
    g_tabA[i] = tA;

    float src = g_src[i];
    float z   = src + dm;
    float lz  = (z > 0.f) ? z : 0.2f * z;
    float mm  = fmaxf(lz, 9e-15f);      // safe row max (adj-independent)
    g_rowc[i] = make_float4(expf(z - mm), expf(0.2f*z - mm),
                            expf(9e-15f - mm), -src);
}

// ---------------- K4: main pass over adj — barrier-free warps ------------
// Warp w owns columns [w*256, w*256+256); lane owns 8 of them (table in regs).
// 4 rows per iteration; per-warp partials finalized by an in-register
// multi-value butterfly transpose-reduce (16 shfl / 4 rows), stored to a
// per-warp smem slab. One __syncthreads total; fused ELU epilogue.
__global__ void __launch_bounds__(NT, 1) k_main(const int* __restrict__ adj) {
    int t = threadIdx.x, w = t >> 5, lane = t & 31;
    int j0 = w * 256 + lane * 8;

    float p[8], q[8], dd[8], h0[8], h1[8], h2[8];
#pragma unroll
    for (int k = 0; k < 8; k++) {
        float4 A = g_tabA[j0 + k];
        float2 B = g_tabB[j0 + k];
        p[k] = A.x; q[k] = A.y; dd[k] = A.z;
        h0[k] = A.w; h1[k] = B.x; h2[k] = B.y;
    }

    __shared__ float sPart[16 * RBLK_MAX * 4];   // 28 KB

    int G = gridDim.x;
    int rblk = (((ROWS_T + G - 1) / G) + 3) & ~3;  // rows per block, mult of 4
    if (rblk > RBLK_MAX) rblk = RBLK_MAX;
    int r_begin = blockIdx.x * rblk;
    int iters = rblk >> 2;

    for (int it = 0; it < iters; it++) {
        int row0 = r_begin + it * 4;

        int4 av[8];
#pragma unroll
        for (int r = 0; r < 4; r++) {
            int rr = min(row0 + r, ROWS_T - 1);
            const int4* ap = (const int4*)adj + (((size_t)rr) << 10) + (j0 >> 2);
            av[2*r]   = __ldg(ap);
            av[2*r+1] = __ldg(ap + 1);
        }

        float v[16];
#pragma unroll
        for (int r = 0; r < 4; r++) {
            int rr = min(row0 + r, ROWS_T - 1);
            float4 rc = __ldg(&g_rowc[rr & (N_ENT - 1)]);
            int va[8];
            *(int4*)&va[0] = av[2*r];
            *(int4*)&va[4] = av[2*r+1];
            float a0 = 0.f, a1 = 0.f, a2 = 0.f, a3 = 0.f;
#pragma unroll
            for (int k = 0; k < 8; k++) {
                float we = (dd[k] > rc.w) ? (rc.x * p[k]) : (rc.y * q[k]);
                float c  = (va[k] > 0) ? we : rc.z;
                a0 += c;
                a1 += c * h0[k];
                a2 += c * h1[k];
                a3 += c * h2[k];
            }
            v[r*4+0] = a0; v[r*4+1] = a1; v[r*4+2] = a2; v[r*4+3] = a3;
        }

        // butterfly transpose-reduce: lane i (i<16) ends with the warp-total
        // of v[i] (= row i>>2, comp i&3)
#pragma unroll
        for (int d = 8; d >= 1; d >>= 1) {
            int bit = (lane & d) ? 1 : 0;
#pragma unroll
            for (int k = 0; k < d; k++) {
                float snd = bit ? v[k] : v[k+d];
                float tmp = __shfl_xor_sync(0xffffffffu, snd, d);
                v[k] = (bit ? v[k+d] : v[k]) + tmp;
            }
        }
        v[0] += __shfl_xor_sync(0xffffffffu, v[0], 16);

        if (lane < 16)
            sPart[w * (RBLK_MAX*4) + it * 16 + lane] = v[0];
    }

    __syncthreads();

    // epilogue: combine 16 warp slabs, h' = num/den, ELU, store x
    for (int r = t; r < rblk; r += NT) {
        int row = r_begin + r;
        if (row >= ROWS_T) break;
        float den = 0.f, n0 = 0.f, n1 = 0.f, n2 = 0.f;
#pragma unroll
        for (int ww = 0; ww < 16; ww++) {
            const float* sp = &sPart[ww * (RBLK_MAX*4) + r * 4];
            den += sp[0]; n0 += sp[1]; n1 += sp[2]; n2 += sp[3];
        }
        float inv = 1.0f / den;
        float x0 = n0 * inv, x1 = n1 * inv, x2 = n2 * inv;
        x0 = (x0 > 0.f) ? x0 : (expf(x0) - 1.f);
        x1 = (x1 > 0.f) ? x1 : (expf(x1) - 1.f);
        x2 = (x2 > 0.f) ? x2 : (expf(x2) - 1.f);
        float* xp = g_x + (size_t)row * NHID;
        xp[0] = x0; xp[1] = x1; xp[2] = x2;
    }
}

// ---------------- K5: out = x @ fc1_w.T + b (400 independent dots) -------
__global__ void k_fc(const float* __restrict__ w,
                     const float* __restrict__ bias,
                     float* __restrict__ out) {
    int o = blockIdx.x;          // 0..99
    int b = blockIdx.y;          // 0..3
    int t = threadIdx.x;         // 256
    const float4* wr = (const float4*)(w + (size_t)o * (N_ENT*NHID));
    const float4* xv = (const float4*)(g_x + (size_t)b * (N_ENT*NHID));
    float acc = 0.f;
#pragma unroll
    for (int k = t; k < (N_ENT*NHID)/4; k += 256) {
        float4 wv = __ldg(wr + k);
        float4 xx = xv[k];
        acc += wv.x*xx.x + wv.y*xx.y + wv.z*xx.z + wv.w*xx.w;
    }
    __shared__ float sr[256];
    sr[t] = acc;
    __syncthreads();
    for (int s = 128; s > 0; s >>= 1) {
        if (t < s) sr[t] += sr[t+s];
        __syncthreads();
    }
    if (t == 0) out[b*100 + o] = sr[0] + bias[o];
}

// ---------------- launcher ----------------
extern "C" void kernel_launch(void* const* d_in, const int* in_sizes, int n_in,
                              void* d_out, int out_size) {
    const int*   adj  = (const int*)  d_in[0];
    const float* emb  = (const float*)d_in[1];
    const float* W    = (const float*)d_in[2];
    const float* a    = (const float*)d_in[3];
    const float* fc1w = (const float*)d_in[4];
    const float* fc1b = (const float*)d_in[5];
    float* out = (float*)d_out;

    k_node  <<<N_ENT/256, 256>>>(emb, W, a);
    k_dstmax<<<1, 1024>>>();
    k_consts<<<N_ENT/256, 256>>>();

    int sms = 148;
    int dev = 0;
    if (cudaGetDevice(&dev) == cudaSuccess) {
        int v = 0;
        if (cudaDeviceGetAttribute(&v, cudaDevAttrMultiProcessorCount, dev) == cudaSuccess && v > 0)
            sms = v;
    }
    k_main<<<sms, NT>>>(adj);

    k_fc<<<dim3(100, BATCH), 256>>>(fc1w, fc1b, out);
}

// round 4
// speedup vs baseline: 1.5134x; 1.0835x over previous
#include <cuda_runtime.h>
#include <math.h>

#define N_ENT 4096
#define BATCH 4
#define NHID  3
#define ROWS_T (BATCH*N_ENT)     // 16384
#define RBLK_MAX 112

// ---------------- device scratch ----------------
__device__ float4  g_tabH[N_ENT];        // h0, h1, h2, dst
__device__ float   g_src[N_ENT];
__device__ unsigned g_dmax_u = 0;        // encoded float max (idempotent across replays)
__device__ float4  g_part[2*ROWS_T];     // per column-half partial (den,n0,n1,n2)
__device__ float   g_x[ROWS_T*NHID];

__device__ __forceinline__ unsigned fenc(float f) {
    unsigned u = __float_as_uint(f);
    return (u & 0x80000000u) ? ~u : (u | 0x80000000u);
}
__device__ __forceinline__ float fdec(unsigned e) {
    return (e & 0x80000000u) ? __uint_as_float(e & 0x7fffffffu)
                             : __uint_as_float(~e);
}

// ---------------- K1: h = emb@W, src/dst per node, atomic dstmax ----------
__global__ void k_node(const float* __restrict__ emb,
                       const float* __restrict__ W,
                       const float* __restrict__ a) {
    __shared__ float sW[192];
    __shared__ float sa[6];
    __shared__ float sm[256];
    int t = threadIdx.x;
    if (t < 192) sW[t] = W[t];
    if (t < 6)   sa[t] = a[t];
    __syncthreads();

    int i = blockIdx.x * blockDim.x + t;
    const float4* ev = (const float4*)(emb + (size_t)i * 64);
    float h0 = 0.f, h1 = 0.f, h2 = 0.f;
#pragma unroll
    for (int k4 = 0; k4 < 16; k4++) {
        float4 e = ev[k4];
        int k = k4 * 4;
        h0 += e.x*sW[k*3+0] + e.y*sW[k*3+3] + e.z*sW[k*3+6] + e.w*sW[k*3+9];
        h1 += e.x*sW[k*3+1] + e.y*sW[k*3+4] + e.z*sW[k*3+7] + e.w*sW[k*3+10];
        h2 += e.x*sW[k*3+2] + e.y*sW[k*3+5] + e.z*sW[k*3+8] + e.w*sW[k*3+11];
    }
    float src = h0*sa[0] + h1*sa[1] + h2*sa[2];
    float dst = h0*sa[3] + h1*sa[4] + h2*sa[5];
    g_tabH[i] = make_float4(h0, h1, h2, dst);
    g_src[i]  = src;

    // block-reduce max(dst) then one atomic per block
    sm[t] = dst;
    __syncthreads();
    for (int s = 128; s > 0; s >>= 1) {
        if (t < s) sm[t] = fmaxf(sm[t], sm[t+s]);
        __syncthreads();
    }
    if (t == 0) atomicMax(&g_dmax_u, fenc(sm[0]));
}

// ---------------- K2: main pass over adj — barrier-free warps ------------
// Grid = 2*SMs. Block pair: pair = bid>>1 owns a row chunk; ch = bid&1 owns
// column half [ch*2048, ch*2048+2048). Warp w owns 256 cols; lane owns 8
// (tables register-resident; p/q computed in prologue). Per-row softmax
// constants cached in smem. 4 rows/iter, in-register butterfly
// transpose-reduce, per-warp smem slab, CTA epilogue writes a float4
// partial per row to g_part.
__global__ void __launch_bounds__(256, 2) k_main(const int* __restrict__ adj) {
    int t = threadIdx.x, w = t >> 5, lane = t & 31;
    int pair = blockIdx.x >> 1, ch = blockIdx.x & 1;
    int j0 = ch * 2048 + w * 256 + lane * 8;

    float dm = fdec(g_dmax_u);

    // per-lane column tables
    float p[8], q[8], h0[8], h1[8], h2[8];
#pragma unroll
    for (int k = 0; k < 8; k++) {
        float4 H = g_tabH[j0 + k];
        h0[k] = H.x; h1[k] = H.y; h2[k] = H.z;
        float d = H.w - dm;
        p[k] = expf(d);
        q[k] = expf(0.2f * d);
    }

    int pairs = gridDim.x >> 1;
    int rblk = (((ROWS_T + pairs - 1) / pairs) + 3) & ~3;
    if (rblk > RBLK_MAX) rblk = RBLK_MAX;
    int r_begin = pair * rblk;
    int iters = rblk >> 2;

    // per-row constants: u, v, w0 (pad)
    __shared__ float4 sRow[RBLK_MAX];
    for (int r = t; r < rblk; r += 256) {
        int row = min(r_begin + r, ROWS_T - 1);
        float src = g_src[row & (N_ENT - 1)];
        float z  = src + dm;
        float lz = fmaxf(z, 0.2f * z);
        float m  = fmaxf(lz, 9e-15f);
        sRow[r] = make_float4(expf(z - m), expf(0.2f*z - m),
                              expf(9e-15f - m), 0.f);
    }
    __syncthreads();

    __shared__ float sPart[8][RBLK_MAX * 4];   // 14 KB

    for (int it = 0; it < iters; it++) {
        int row0 = r_begin + it * 4;

        int4 av[8];
#pragma unroll
        for (int r = 0; r < 4; r++) {
            int rr = min(row0 + r, ROWS_T - 1);
            const int4* ap = (const int4*)adj + (((size_t)rr) << 10) + (j0 >> 2);
            av[2*r]   = __ldg(ap);
            av[2*r+1] = __ldg(ap + 1);
        }

        float v[16];
#pragma unroll
        for (int r = 0; r < 4; r++) {
            float4 rc = sRow[it*4 + r];     // u, v, w0 (broadcast LDS.128)
            int va[8];
            *(int4*)&va[0] = av[2*r];
            *(int4*)&va[4] = av[2*r+1];
            float a0 = 0.f, a1 = 0.f, a2 = 0.f, a3 = 0.f;
#pragma unroll
            for (int k = 0; k < 8; k++) {
                float we = fmaxf(rc.x * p[k], rc.y * q[k]);
                float c  = (va[k] > 0) ? we : rc.z;
                a0 += c;
                a1 += c * h0[k];
                a2 += c * h1[k];
                a3 += c * h2[k];
            }
            v[r*4+0] = a0; v[r*4+1] = a1; v[r*4+2] = a2; v[r*4+3] = a3;
        }

        // butterfly transpose-reduce: lane i (i<16) ends with the warp-total
        // of v[i] (= row i>>2, comp i&3)
#pragma unroll
        for (int d = 8; d >= 1; d >>= 1) {
            int bit = (lane & d) ? 1 : 0;
#pragma unroll
            for (int k = 0; k < d; k++) {
                float snd = bit ? v[k] : v[k+d];
                float tmp = __shfl_xor_sync(0xffffffffu, snd, d);
                v[k] = (bit ? v[k+d] : v[k]) + tmp;
            }
        }
        v[0] += __shfl_xor_sync(0xffffffffu, v[0], 16);

        if (lane < 16)
            sPart[w][it * 16 + lane] = v[0];
    }

    __syncthreads();

    // CTA epilogue: combine 8 warp slabs -> per-row partial float4
    for (int r = t; r < rblk; r += 256) {
        int row = r_begin + r;
        if (row >= ROWS_T) break;
        float den = 0.f, n0 = 0.f, n1 = 0.f, n2 = 0.f;
#pragma unroll
        for (int ww = 0; ww < 8; ww++) {
            const float* sp = &sPart[ww][r * 4];
            den += sp[0]; n0 += sp[1]; n1 += sp[2]; n2 += sp[3];
        }
        g_part[(size_t)ch * ROWS_T + row] = make_float4(den, n0, n1, n2);
    }
}

// ---------------- K3: combine halves, h'=num/den, ELU, build x -----------
__global__ void k_x() {
    int idx = blockIdx.x * blockDim.x + threadIdx.x;   // 16384
    float4 A = g_part[idx];
    float4 B = g_part[ROWS_T + idx];
    float inv = 1.0f / (A.x + B.x);
    float x0 = (A.y + B.y) * inv;
    float x1 = (A.z + B.z) * inv;
    float x2 = (A.w + B.w) * inv;
    x0 = (x0 > 0.f) ? x0 : (expf(x0) - 1.f);
    x1 = (x1 > 0.f) ? x1 : (expf(x1) - 1.f);
    x2 = (x2 > 0.f) ? x2 : (expf(x2) - 1.f);
    float* xp = g_x + (size_t)idx * NHID;
    xp[0] = x0; xp[1] = x1; xp[2] = x2;
}

// ---------------- K4: out = x @ fc1_w.T + b (400 independent dots) -------
__global__ void k_fc(const float* __restrict__ w,
                     const float* __restrict__ bias,
                     float* __restrict__ out) {
    int o = blockIdx.x;          // 0..99
    int b = blockIdx.y;          // 0..3
    int t = threadIdx.x;         // 256
    const float4* wr = (const float4*)(w + (size_t)o * (N_ENT*NHID));
    const float4* xv = (const float4*)(g_x + (size_t)b * (N_ENT*NHID));
    float acc = 0.f;
#pragma unroll
    for (int k = t; k < (N_ENT*NHID)/4; k += 256) {
        float4 wv = __ldg(wr + k);
        float4 xx = xv[k];
        acc += wv.x*xx.x + wv.y*xx.y + wv.z*xx.z + wv.w*xx.w;
    }
    __shared__ float sr[256];
    sr[t] = acc;
    __syncthreads();
    for (int s = 128; s > 0; s >>= 1) {
        if (t < s) sr[t] += sr[t+s];
        __syncthreads();
    }
    if (t == 0) out[b*100 + o] = sr[0] + bias[o];
}

// ---------------- launcher ----------------
extern "C" void kernel_launch(void* const* d_in, const int* in_sizes, int n_in,
                              void* d_out, int out_size) {
    const int*   adj  = (const int*)  d_in[0];
    const float* emb  = (const float*)d_in[1];
    const float* W    = (const float*)d_in[2];
    const float* a    = (const float*)d_in[3];
    const float* fc1w = (const float*)d_in[4];
    const float* fc1b = (const float*)d_in[5];
    float* out = (float*)d_out;

    k_node<<<N_ENT/256, 256>>>(emb, W, a);

    int sms = 148;
    int dev = 0;
    if (cudaGetDevice(&dev) == cudaSuccess) {
        int v = 0;
        if (cudaDeviceGetAttribute(&v, cudaDevAttrMultiProcessorCount, dev) == cudaSuccess && v > 0)
            sms = v;
    }
    k_main<<<2*sms, 256>>>(adj);

    k_x <<<ROWS_T/256, 256>>>();
    k_fc<<<dim3(100, BATCH), 256>>>(fc1w, fc1b, out);
}